// round 6
// baseline (speedup 1.0000x reference)
#include <cuda_runtime.h>
#include <cuda_bf16.h>
#include <cstdint>

#define Bq 8
#define Nq 1024
#define Cq 768
#define Hq 12
#define HDq 64
#define Rq 16
#define ROWS (Bq*Nq)
#define SCALE 0.125f

typedef unsigned long long ull;
typedef __nv_bfloat16 bf16;

// ---------------- mma.sync / ldmatrix / cp.async helpers ----------------
__device__ __forceinline__ uint32_t smem_u32(const void* p) {
    uint32_t a;
    asm("{ .reg .u64 t; cvta.to.shared.u64 t, %1; cvt.u32.u64 %0, t; }" : "=r"(a) : "l"(p));
    return a;
}
__device__ __forceinline__ void ldsm4(uint32_t& r0, uint32_t& r1, uint32_t& r2, uint32_t& r3,
                                      uint32_t addr) {
    asm volatile("ldmatrix.sync.aligned.m8n8.x4.shared.b16 {%0,%1,%2,%3}, [%4];"
                 : "=r"(r0), "=r"(r1), "=r"(r2), "=r"(r3) : "r"(addr));
}
__device__ __forceinline__ void ldsm4t(uint32_t& r0, uint32_t& r1, uint32_t& r2, uint32_t& r3,
                                       uint32_t addr) {
    asm volatile("ldmatrix.sync.aligned.m8n8.x4.trans.shared.b16 {%0,%1,%2,%3}, [%4];"
                 : "=r"(r0), "=r"(r1), "=r"(r2), "=r"(r3) : "r"(addr));
}
__device__ __forceinline__ void mma_bf16(float* c, uint32_t a0, uint32_t a1, uint32_t a2,
                                         uint32_t a3, uint32_t b0, uint32_t b1) {
    asm("mma.sync.aligned.m16n8k16.row.col.f32.bf16.bf16.f32 "
        "{%0,%1,%2,%3}, {%4,%5,%6,%7}, {%8,%9}, {%0,%1,%2,%3};"
        : "+f"(c[0]), "+f"(c[1]), "+f"(c[2]), "+f"(c[3])
        : "r"(a0), "r"(a1), "r"(a2), "r"(a3), "r"(b0), "r"(b1));
}
__device__ __forceinline__ void cp16(uint32_t dst, const void* src) {
    asm volatile("cp.async.cg.shared.global [%0], [%1], 16;" :: "r"(dst), "l"(src));
}
__device__ __forceinline__ void cp_commit() {
    asm volatile("cp.async.commit_group;" ::: "memory");
}
template <int N>
__device__ __forceinline__ void cp_wait() {
    asm volatile("cp.async.wait_group %0;" :: "n"(N) : "memory");
}

__device__ __forceinline__ void split_bf16(float v, bf16& h, bf16& l) {
    h = __float2bfloat16(v);
    l = __float2bfloat16(v - __bfloat162float(h));
}
__device__ __forceinline__ uint32_t pkbf(bf16 a, bf16 b) {
    __nv_bfloat162 t; t.x = a; t.y = b;
    return *(uint32_t*)&t;
}

// ---------------- scratch ----------------
__device__ bf16 g_qh[Bq*Hq*Nq*HDq], g_ql[Bq*Hq*Nq*HDq];
__device__ bf16 g_kh[Bq*Hq*Nq*HDq], g_kl[Bq*Hq*Nq*HDq];
__device__ bf16 g_vh[Bq*Hq*Nq*HDq], g_vl[Bq*Hq*Nq*HDq];
__device__ bf16 g_Xh[ROWS*Cq], g_Xl[ROWS*Cq];
__device__ bf16 g_Wth[3][Cq*Cq], g_Wtl[3][Cq*Cq];
__device__ bf16 g_Wpth[Cq*Cq], g_Wptl[Cq*Cq];
__device__ bf16 g_XAh[3][ROWS*32], g_XAl[3][ROWS*32];
__device__ bf16 g_LBh[3][Cq*32], g_LBl[3][Cq*32];
__device__ bf16 g_atth[ROWS*Cq], g_attl[ROWS*Cq];

// ---------------- prep kernels ----------------
__global__ void convert_x_kernel(const float* __restrict__ X) {
    int i = blockIdx.x * blockDim.x + threadIdx.x;
    if (i < ROWS * Cq) {
        bf16 h, l; split_bf16(X[i], h, l);
        g_Xh[i] = h; g_Xl[i] = l;
    }
}

__global__ void transpose_w_kernel(const float* __restrict__ Wq_, const float* __restrict__ Wk_,
                                   const float* __restrict__ Wv_, const float* __restrict__ Wp_) {
    __shared__ float sh[32][33];
    int sel = blockIdx.z;
    const float* W = (sel == 0) ? Wq_ : (sel == 1) ? Wk_ : (sel == 2) ? Wv_ : Wp_;
    bf16* dh = (sel < 3) ? g_Wth[sel] : g_Wpth;
    bf16* dl = (sel < 3) ? g_Wtl[sel] : g_Wptl;
    int tx = threadIdx.x & 31, ty = threadIdx.x >> 5;
    int kb = blockIdx.y * 32, nb = blockIdx.x * 32;
    #pragma unroll
    for (int i = 0; i < 4; i++)
        sh[ty + i * 8][tx] = W[(size_t)(kb + ty + i * 8) * Cq + nb + tx];
    __syncthreads();
    #pragma unroll
    for (int i = 0; i < 4; i++) {
        float v = sh[tx][ty + i * 8];
        bf16 h, l; split_bf16(v, h, l);
        size_t idx = (size_t)(nb + ty + i * 8) * Cq + kb + tx;
        dh[idx] = h; dl[idx] = l;
    }
}

__global__ void transpose_lb_kernel(const float* __restrict__ lbq,
                                    const float* __restrict__ lbk,
                                    const float* __restrict__ lbv) {
    int idx = blockIdx.x * blockDim.x + threadIdx.x;
    if (idx >= 3 * Cq * 32) return;
    int t = idx / (Cq * 32);
    int rem = idx - t * Cq * 32;
    int n = rem >> 5, r = rem & 31;
    const float* lb = (t == 0) ? lbq : (t == 1) ? lbk : lbv;
    float v = (r < Rq) ? lb[r * Cq + n] : 0.f;
    bf16 h, l; split_bf16(v, h, l);
    g_LBh[t][n * 32 + r] = h; g_LBl[t][n * 32 + r] = l;
}

// 1024 threads, 4-way k-split + shfl reduce
__global__ __launch_bounds__(1024) void lora_xa_kernel(const float* __restrict__ X,
                               const float* __restrict__ la_q,
                               const float* __restrict__ la_k,
                               const float* __restrict__ la_v,
                               const float* __restrict__ bw) {
    __shared__ float xs[16][Cq];
    int tid = threadIdx.x;
    int rowBase = blockIdx.x * 16;
    for (int l = tid; l < 16 * Cq; l += 1024) {
        int r = l / Cq, c = l % Cq;
        xs[r][c] = X[(size_t)(rowBase + r) * Cq + c];
    }
    __syncthreads();
    int r = tid >> 6;          // 0..15
    int c = (tid >> 2) & 15;   // 0..15
    int ks = tid & 3;          // 0..3
    float aq = 0.f, ak = 0.f, av = 0.f;
    int k0 = ks * 192;
    #pragma unroll 8
    for (int k = k0; k < k0 + 192; k++) {
        float xv = xs[r][k];
        aq = fmaf(xv, la_q[k * Rq + c], aq);
        ak = fmaf(xv, la_k[k * Rq + c], ak);
        av = fmaf(xv, la_v[k * Rq + c], av);
    }
    aq += __shfl_xor_sync(0xffffffffu, aq, 1); aq += __shfl_xor_sync(0xffffffffu, aq, 2);
    ak += __shfl_xor_sync(0xffffffffu, ak, 1); ak += __shfl_xor_sync(0xffffffffu, ak, 2);
    av += __shfl_xor_sync(0xffffffffu, av, 1); av += __shfl_xor_sync(0xffffffffu, av, 2);
    if (ks == 0) {
        int row = rowBase + r;
        bf16 h, l;
        split_bf16(bw[0] * aq, h, l); g_XAh[0][row * 32 + c] = h; g_XAl[0][row * 32 + c] = l;
        split_bf16(bw[1] * ak, h, l); g_XAh[1][row * 32 + c] = h; g_XAl[1][row * 32 + c] = l;
        split_bf16(bw[2] * av, h, l); g_XAh[2][row * 32 + c] = h; g_XAl[2][row * 32 + c] = l;
    }
    if (tid < 256) {
        int rr = tid >> 4, cc = 16 + (tid & 15);
        int rowz = rowBase + rr;
        #pragma unroll
        for (int t = 0; t < 3; t++) {
            g_XAh[t][rowz * 32 + cc] = __float2bfloat16(0.f);
            g_XAl[t][rowz * 32 + cc] = __float2bfloat16(0.f);
        }
    }
}

// ---------------- pipelined bf16 GEMM core ----------------
#define PITCH 40
#define NSTAGE 4
#define TILE_B 10240
#define STAGE_B (4*TILE_B)
#define GEMM_DSMEM (NSTAGE*STAGE_B)

__device__ __forceinline__ void issue_chunk(uint32_t sbase, int stage,
                                            const bf16* ah, const bf16* al,
                                            const bf16* bh, const bf16* bl,
                                            int stride, int tid) {
    uint32_t st = sbase + stage * STAGE_B;
    const bf16* srcs[4] = {ah, al, bh, bl};
    #pragma unroll
    for (int t = 0; t < 4; t++) {
        #pragma unroll
        for (int i = 0; i < 2; i++) {
            int idx = tid + 256 * i;
            int row = idx >> 2, seg = idx & 3;
            cp16(st + t * TILE_B + (row * PITCH + seg * 8) * 2,
                 srcs[t] + (size_t)row * stride + seg * 8);
        }
    }
    cp_commit();
}

__device__ __forceinline__ void compute_chunk(uint32_t sbase, int stage,
                                              float C[2][8][4], int a_off, int b_off) {
    uint32_t st = sbase + stage * STAGE_B;
    uint32_t aH = st, aL = st + TILE_B, bH = st + 2 * TILE_B, bL = st + 3 * TILE_B;
    #pragma unroll
    for (int kt = 0; kt < 2; kt++) {
        int ko = kt * 16;
        uint32_t ah[2][4], al[2][4], bh[8][2], bl[8][2];
        #pragma unroll
        for (int mt = 0; mt < 2; mt++) {
            int off = (a_off + mt * 16 * PITCH + ko) * 2;
            ldsm4(ah[mt][0], ah[mt][1], ah[mt][2], ah[mt][3], aH + off);
            ldsm4(al[mt][0], al[mt][1], al[mt][2], al[mt][3], aL + off);
        }
        #pragma unroll
        for (int p = 0; p < 4; p++) {
            int off = (b_off + p * 16 * PITCH + ko) * 2;
            ldsm4(bh[2*p][0], bh[2*p][1], bh[2*p+1][0], bh[2*p+1][1], bH + off);
            ldsm4(bl[2*p][0], bl[2*p][1], bl[2*p+1][0], bl[2*p+1][1], bL + off);
        }
        #pragma unroll
        for (int mt = 0; mt < 2; mt++)
            #pragma unroll
            for (int nt = 0; nt < 8; nt++) {
                mma_bf16(C[mt][nt], ah[mt][0], ah[mt][1], ah[mt][2], ah[mt][3],
                         bh[nt][0], bh[nt][1]);
                mma_bf16(C[mt][nt], ah[mt][0], ah[mt][1], ah[mt][2], ah[mt][3],
                         bl[nt][0], bl[nt][1]);
                mma_bf16(C[mt][nt], al[mt][0], al[mt][1], al[mt][2], al[mt][3],
                         bh[nt][0], bh[nt][1]);
            }
    }
}

// ---------------- qkv GEMM -> bf16 hi/lo head-split (q pre-scaled by 1/8) ----------------
__global__ __launch_bounds__(256) void gemm_qkv_kernel() {
    extern __shared__ char dsm[];
    uint32_t sbase = smem_u32(dsm);
    int tid = threadIdx.x, lid = tid & 31, wid = tid >> 5;
    int wm = (wid & 3) * 32, wn = (wid >> 2) * 64;
    int type = blockIdx.z;
    int rowBase = blockIdx.y * 128, colBase = blockIdx.x * 128;

    const bf16* Xh = g_Xh + (size_t)rowBase * Cq;
    const bf16* Xl = g_Xl + (size_t)rowBase * Cq;
    const bf16* Wh = g_Wth[type] + (size_t)colBase * Cq;
    const bf16* Wl = g_Wtl[type] + (size_t)colBase * Cq;
    const bf16* XAh = g_XAh[type] + (size_t)rowBase * 32;
    const bf16* XAl = g_XAl[type] + (size_t)rowBase * 32;
    const bf16* LBh = g_LBh[type] + (size_t)colBase * 32;
    const bf16* LBl = g_LBl[type] + (size_t)colBase * 32;

    float C[2][8][4];
    #pragma unroll
    for (int i = 0; i < 2; i++)
        #pragma unroll
        for (int j = 0; j < 8; j++)
            #pragma unroll
            for (int k = 0; k < 4; k++) C[i][j][k] = 0.f;

    int a_off = (wm + (lid & 15)) * PITCH + ((lid >> 4) & 1) * 8;
    int b_off = (wn + ((lid >> 4) & 1) * 8 + (lid & 7)) * PITCH + ((lid >> 3) & 1) * 8;

    const int NCH = 25;
    #pragma unroll
    for (int s = 0; s < NSTAGE - 1; s++) {
        if (s < 24)
            issue_chunk(sbase, s, Xh + s * 32, Xl + s * 32, Wh + s * 32, Wl + s * 32, Cq, tid);
        else
            issue_chunk(sbase, s, XAh, XAl, LBh, LBl, 32, tid);
    }
    for (int c = 0; c < NCH; c++) {
        cp_wait<NSTAGE - 2>();
        __syncthreads();
        int nc = c + NSTAGE - 1;
        if (nc < NCH) {
            int st = nc & (NSTAGE - 1);
            if (nc < 24)
                issue_chunk(sbase, st, Xh + nc * 32, Xl + nc * 32, Wh + nc * 32, Wl + nc * 32, Cq, tid);
            else
                issue_chunk(sbase, st, XAh, XAl, LBh, LBl, 32, tid);
        } else {
            cp_commit();
        }
        compute_chunk(sbase, c & (NSTAGE - 1), C, a_off, b_off);
    }

    bf16* outh = (type == 0) ? g_qh : (type == 1) ? g_kh : g_vh;
    bf16* outl = (type == 0) ? g_ql : (type == 1) ? g_kl : g_vl;
    float scl = (type == 0) ? SCALE : 1.f;   // fold 1/sqrt(HD) into q (exact pow2)
    #pragma unroll
    for (int mt = 0; mt < 2; mt++)
        #pragma unroll
        for (int nt = 0; nt < 8; nt++) {
            int col = colBase + wn + nt * 8 + (lid & 3) * 2;
            int h = col >> 6, hd = col & 63;
            #pragma unroll
            for (int half = 0; half < 2; half++) {
                int row = rowBase + wm + mt * 16 + (lid >> 2) + half * 8;
                int b_ = row >> 10, n = row & 1023;
                float v0 = C[mt][nt][half * 2] * scl, v1 = C[mt][nt][half * 2 + 1] * scl;
                bf16 h0, l0, h1, l1;
                split_bf16(v0, h0, l0); split_bf16(v1, h1, l1);
                size_t base = (((size_t)(b_ * Hq + h) * Nq) + n) * HDq + hd;
                *(uint32_t*)&outh[base] = pkbf(h0, h1);
                *(uint32_t*)&outl[base] = pkbf(l0, l1);
            }
        }
}

// ---------------- output projection GEMM + bias ----------------
__global__ __launch_bounds__(256) void gemm_out_kernel(const float* __restrict__ bias,
                                                       float* __restrict__ out) {
    extern __shared__ char dsm[];
    uint32_t sbase = smem_u32(dsm);
    int tid = threadIdx.x, lid = tid & 31, wid = tid >> 5;
    int wm = (wid & 3) * 32, wn = (wid >> 2) * 64;
    int rowBase = blockIdx.y * 128, colBase = blockIdx.x * 128;

    const bf16* Ah = g_atth + (size_t)rowBase * Cq;
    const bf16* Al = g_attl + (size_t)rowBase * Cq;
    const bf16* Wh = g_Wpth + (size_t)colBase * Cq;
    const bf16* Wl = g_Wptl + (size_t)colBase * Cq;

    float C[2][8][4];
    #pragma unroll
    for (int i = 0; i < 2; i++)
        #pragma unroll
        for (int j = 0; j < 8; j++)
            #pragma unroll
            for (int k = 0; k < 4; k++) C[i][j][k] = 0.f;

    int a_off = (wm + (lid & 15)) * PITCH + ((lid >> 4) & 1) * 8;
    int b_off = (wn + ((lid >> 4) & 1) * 8 + (lid & 7)) * PITCH + ((lid >> 3) & 1) * 8;

    const int NCH = 24;
    #pragma unroll
    for (int s = 0; s < NSTAGE - 1; s++)
        issue_chunk(sbase, s, Ah + s * 32, Al + s * 32, Wh + s * 32, Wl + s * 32, Cq, tid);
    for (int c = 0; c < NCH; c++) {
        cp_wait<NSTAGE - 2>();
        __syncthreads();
        int nc = c + NSTAGE - 1;
        if (nc < NCH)
            issue_chunk(sbase, nc & (NSTAGE - 1), Ah + nc * 32, Al + nc * 32,
                        Wh + nc * 32, Wl + nc * 32, Cq, tid);
        else
            cp_commit();
        compute_chunk(sbase, c & (NSTAGE - 1), C, a_off, b_off);
    }

    #pragma unroll
    for (int mt = 0; mt < 2; mt++)
        #pragma unroll
        for (int nt = 0; nt < 8; nt++) {
            int col = colBase + wn + nt * 8 + (lid & 3) * 2;
            float2 bv = *(const float2*)&bias[col];
            #pragma unroll
            for (int half = 0; half < 2; half++) {
                int row = rowBase + wm + mt * 16 + (lid >> 2) + half * 8;
                float2 v = make_float2(C[mt][nt][half * 2] + bv.x, C[mt][nt][half * 2 + 1] + bv.y);
                *(float2*)&out[(size_t)row * Cq + col] = v;
            }
        }
}

// ---------------- mma flash attention ----------------
#define QP 72
#define KP 72
#define VPI 72
#define SPI 68
#define PP 72
// smem offsets (bytes)
#define OFF_QH 0
#define OFF_QL 18432
#define OFF_KV 36864          // 2 bufs x 36864 (Kh,Kl,Vh,Vl @ 9216 each)
#define OFF_SS 110592         // 128*68*4
#define OFF_PH 145408
#define OFF_PL 163840
#define OFF_MR 182272
#define OFF_LR 182784
#define OFF_AR 183296
#define ATTN_SMEM 183808

__global__ __launch_bounds__(256, 1) void attn_kernel() {
    extern __shared__ char smx[];
    uint32_t sb = smem_u32(smx);
    float* Ss   = (float*)(smx + OFF_SS);
    bf16*  Ph   = (bf16*)(smx + OFF_PH);
    bf16*  Pl   = (bf16*)(smx + OFF_PL);
    float* mrow = (float*)(smx + OFF_MR);
    float* lrow = (float*)(smx + OFF_LR);
    float* arow = (float*)(smx + OFF_AR);

    int tid = threadIdx.x, lid = tid & 31, wid = tid >> 5;
    int wm = (wid & 3) * 32, wn = (wid >> 2) * 32;   // wn doubles as wd for PV
    int qt = blockIdx.x, h = blockIdx.y, b = blockIdx.z;
    size_t bh = (size_t)(b * Hq + h) * Nq * HDq;
    const bf16* Qhg = g_qh + bh + (size_t)qt * 128 * HDq;
    const bf16* Qlg = g_ql + bh + (size_t)qt * 128 * HDq;

    // prologue: Q + first KV tile
    #pragma unroll
    for (int i = 0; i < 4; i++) {
        int idx = tid + 256 * i;          // 1024 = 128 rows x 8 segs
        int row = idx >> 3, seg = idx & 7;
        cp16(sb + OFF_QH + (row * QP + seg * 8) * 2, Qhg + row * HDq + seg * 8);
        cp16(sb + OFF_QL + (row * QP + seg * 8) * 2, Qlg + row * HDq + seg * 8);
    }
    {
        const bf16* srcs[4] = {g_kh + bh, g_kl + bh, g_vh + bh, g_vl + bh};
        #pragma unroll
        for (int t = 0; t < 4; t++) {
            #pragma unroll
            for (int i = 0; i < 2; i++) {
                int idx = tid + 256 * i;  // 512 = 64 rows x 8 segs
                int row = idx >> 3, seg = idx & 7;
                cp16(sb + OFF_KV + t * 9216 + (row * KP + seg * 8) * 2,
                     srcs[t] + row * HDq + seg * 8);
            }
        }
    }
    cp_commit();
    if (tid < 128) { mrow[tid] = -1e30f; lrow[tid] = 0.f; }

    float Co[2][4][4];
    #pragma unroll
    for (int i = 0; i < 2; i++)
        #pragma unroll
        for (int j = 0; j < 4; j++)
            #pragma unroll
            for (int k = 0; k < 4; k++) Co[i][j][k] = 0.f;

    for (int it = 0; it < 16; it++) {
        // prefetch next KV
        if (it + 1 < 16) {
            uint32_t dst = sb + OFF_KV + ((it + 1) & 1) * 36864;
            const bf16* srcs[4] = {g_kh + bh + (it + 1) * 64 * HDq, g_kl + bh + (it + 1) * 64 * HDq,
                                   g_vh + bh + (it + 1) * 64 * HDq, g_vl + bh + (it + 1) * 64 * HDq};
            #pragma unroll
            for (int t = 0; t < 4; t++) {
                #pragma unroll
                for (int i = 0; i < 2; i++) {
                    int idx = tid + 256 * i;
                    int row = idx >> 3, seg = idx & 7;
                    cp16(dst + t * 9216 + (row * KP + seg * 8) * 2, srcs[t] + row * HDq + seg * 8);
                }
            }
        }
        cp_commit();
        cp_wait<1>();
        __syncthreads();

        uint32_t kv = sb + OFF_KV + (it & 1) * 36864;
        uint32_t aQh = sb + OFF_QH, aQl = sb + OFF_QL;
        uint32_t aKh = kv, aKl = kv + 9216, aVh = kv + 18432, aVl = kv + 27648;

        // ---- S = Q K^T (3-pass hi/lo), S tile 128x64, warp m32 x n32 ----
        float Cs[2][4][4];
        #pragma unroll
        for (int i = 0; i < 2; i++)
            #pragma unroll
            for (int j = 0; j < 4; j++)
                #pragma unroll
                for (int k = 0; k < 4; k++) Cs[i][j][k] = 0.f;

        #pragma unroll
        for (int ks = 0; ks < 4; ks++) {
            int ko = ks * 16;
            uint32_t qh[2][4], ql[2][4], kh[4][2], kl[4][2];
            #pragma unroll
            for (int mt = 0; mt < 2; mt++) {
                int off = ((wm + mt * 16 + (lid & 15)) * QP + ((lid >> 4) & 1) * 8 + ko) * 2;
                ldsm4(qh[mt][0], qh[mt][1], qh[mt][2], qh[mt][3], aQh + off);
                ldsm4(ql[mt][0], ql[mt][1], ql[mt][2], ql[mt][3], aQl + off);
            }
            #pragma unroll
            for (int p = 0; p < 2; p++) {
                int off = ((wn + p * 16 + ((lid >> 4) & 1) * 8 + (lid & 7)) * KP
                           + ((lid >> 3) & 1) * 8 + ko) * 2;
                ldsm4(kh[2*p][0], kh[2*p][1], kh[2*p+1][0], kh[2*p+1][1], aKh + off);
                ldsm4(kl[2*p][0], kl[2*p][1], kl[2*p+1][0], kl[2*p+1][1], aKl + off);
            }
            #pragma unroll
            for (int mt = 0; mt < 2; mt++)
                #pragma unroll
                for (int nt = 0; nt < 4; nt++) {
                    mma_bf16(Cs[mt][nt], qh[mt][0], qh[mt][1], qh[mt][2], qh[mt][3],
                             kh[nt][0], kh[nt][1]);
                    mma_bf16(Cs[mt][nt], qh[mt][0], qh[mt][1], qh[mt][2], qh[mt][3],
                             kl[nt][0], kl[nt][1]);
                    mma_bf16(Cs[mt][nt], ql[mt][0], ql[mt][1], ql[mt][2], ql[mt][3],
                             kh[nt][0], kh[nt][1]);
                }
        }
        // store S to smem (fp32)
        #pragma unroll
        for (int mt = 0; mt < 2; mt++)
            #pragma unroll
            for (int nt = 0; nt < 4; nt++) {
                int r0 = wm + mt * 16 + (lid >> 2);
                int cc = wn + nt * 8 + (lid & 3) * 2;
                *(float2*)&Ss[r0 * SPI + cc] = make_float2(Cs[mt][nt][0], Cs[mt][nt][1]);
                *(float2*)&Ss[(r0 + 8) * SPI + cc] = make_float2(Cs[mt][nt][2], Cs[mt][nt][3]);
            }
        __syncthreads();

        // ---- online softmax: 2 threads per row, 32 cols each ----
        {
            int row = tid >> 1, half = tid & 1;
            int jb = half * 32;
            float mx = -1e30f;
            #pragma unroll 8
            for (int j = 0; j < 32; j++) mx = fmaxf(mx, Ss[row * SPI + jb + j]);
            mx = fmaxf(mx, __shfl_xor_sync(0xffffffffu, mx, 1));
            float mprev = mrow[row];
            float mnew = fmaxf(mprev, mx);
            float sum = 0.f;
            #pragma unroll 8
            for (int j = 0; j < 32; j += 2) {
                float p0 = __expf(Ss[row * SPI + jb + j] - mnew);
                float p1 = __expf(Ss[row * SPI + jb + j + 1] - mnew);
                sum += p0 + p1;
                bf16 h0, l0, h1, l1;
                split_bf16(p0, h0, l0); split_bf16(p1, h1, l1);
                *(uint32_t*)&Ph[row * PP + jb + j] = pkbf(h0, h1);
                *(uint32_t*)&Pl[row * PP + jb + j] = pkbf(l0, l1);
            }
            sum += __shfl_xor_sync(0xffffffffu, sum, 1);
            if (half == 0) {
                float al = __expf(mprev - mnew);
                mrow[row] = mnew;
                lrow[row] = lrow[row] * al + sum;
                arow[row] = al;
            }
        }
        __syncthreads();

        // ---- rescale O, then O += P V (3-pass, V via ldmatrix.trans) ----
        #pragma unroll
        for (int mt = 0; mt < 2; mt++) {
            float a0 = arow[wm + mt * 16 + (lid >> 2)];
            float a1 = arow[wm + mt * 16 + (lid >> 2) + 8];
            #pragma unroll
            for (int nt = 0; nt < 4; nt++) {
                Co[mt][nt][0] *= a0; Co[mt][nt][1] *= a0;
                Co[mt][nt][2] *= a1; Co[mt][nt][3] *= a1;
            }
        }
        uint32_t aPh = sb + OFF_PH, aPl = sb + OFF_PL;
        #pragma unroll
        for (int ks = 0; ks < 4; ks++) {
            int ko = ks * 16;
            uint32_t ph[2][4], pl[2][4], vh[4][2], vl[4][2];
            #pragma unroll
            for (int mt = 0; mt < 2; mt++) {
                int off = ((wm + mt * 16 + (lid & 15)) * PP + ((lid >> 4) & 1) * 8 + ko) * 2;
                ldsm4(ph[mt][0], ph[mt][1], ph[mt][2], ph[mt][3], aPh + off);
                ldsm4(pl[mt][0], pl[mt][1], pl[mt][2], pl[mt][3], aPl + off);
            }
            #pragma unroll
            for (int dt = 0; dt < 2; dt++) {
                int off = ((ko + (lid & 15)) * VPI + wn + dt * 16 + ((lid >> 4) & 1) * 8) * 2;
                ldsm4t(vh[2*dt][0], vh[2*dt][1], vh[2*dt+1][0], vh[2*dt+1][1], aVh + off);
                ldsm4t(vl[2*dt][0], vl[2*dt][1], vl[2*dt+1][0], vl[2*dt+1][1], aVl + off);
            }
            #pragma unroll
            for (int mt = 0; mt < 2; mt++)
                #pragma unroll
                for (int nt = 0; nt < 4; nt++) {
                    mma_bf16(Co[mt][nt], ph[mt][0], ph[mt][1], ph[mt][2], ph[mt][3],
                             vh[nt][0], vh[nt][1]);
                    mma_bf16(Co[mt][nt], ph[mt][0], ph[mt][1], ph[mt][2], ph[mt][3],
                             vl[nt][0], vl[nt][1]);
                    mma_bf16(Co[mt][nt], pl[mt][0], pl[mt][1], pl[mt][2], pl[mt][3],
                             vh[nt][0], vh[nt][1]);
                }
        }
        __syncthreads();
    }

    // ---- epilogue: normalize, write bf16 hi/lo to g_att [B,N,C] ----
    #pragma unroll
    for (int mt = 0; mt < 2; mt++) {
        float inv0 = 1.f / lrow[wm + mt * 16 + (lid >> 2)];
        float inv1 = 1.f / lrow[wm + mt * 16 + (lid >> 2) + 8];
        #pragma unroll
        for (int nt = 0; nt < 4; nt++) {
            int col = h * HDq + wn + nt * 8 + (lid & 3) * 2;
            int r0 = qt * 128 + wm + mt * 16 + (lid >> 2);
            float v0 = Co[mt][nt][0] * inv0, v1 = Co[mt][nt][1] * inv0;
            float v2 = Co[mt][nt][2] * inv1, v3 = Co[mt][nt][3] * inv1;
            bf16 h0, l0, h1, l1;
            split_bf16(v0, h0, l0); split_bf16(v1, h1, l1);
            size_t base = (size_t)(b * Nq + r0) * Cq + col;
            *(uint32_t*)&g_atth[base] = pkbf(h0, h1);
            *(uint32_t*)&g_attl[base] = pkbf(l0, l1);
            split_bf16(v2, h0, l0); split_bf16(v3, h1, l1);
            size_t base2 = (size_t)(b * Nq + r0 + 8) * Cq + col;
            *(uint32_t*)&g_atth[base2] = pkbf(h0, h1);
            *(uint32_t*)&g_attl[base2] = pkbf(l0, l1);
        }
    }
}

extern "C" void kernel_launch(void* const* d_in, const int* in_sizes, int n_in,
                              void* d_out, int out_size) {
    const float* x    = (const float*)d_in[0];
    const float* Wq   = (const float*)d_in[1];
    const float* Wk   = (const float*)d_in[2];
    const float* Wv   = (const float*)d_in[3];
    const float* Wp   = (const float*)d_in[4];
    const float* bp   = (const float*)d_in[5];
    const float* la_q = (const float*)d_in[6];
    const float* lb_q = (const float*)d_in[7];
    const float* la_k = (const float*)d_in[8];
    const float* lb_k = (const float*)d_in[9];
    const float* la_v = (const float*)d_in[10];
    const float* lb_v = (const float*)d_in[11];
    const float* bw   = (const float*)d_in[12];
    float* out = (float*)d_out;

    convert_x_kernel<<<(ROWS * Cq + 255) / 256, 256>>>(x);
    transpose_w_kernel<<<dim3(24, 24, 4), 256>>>(Wq, Wk, Wv, Wp);
    transpose_lb_kernel<<<(3 * Cq * 32 + 255) / 256, 256>>>(lb_q, lb_k, lb_v);
    lora_xa_kernel<<<ROWS / 16, 1024>>>(x, la_q, la_k, la_v, bw);

    cudaFuncSetAttribute(gemm_qkv_kernel, cudaFuncAttributeMaxDynamicSharedMemorySize, GEMM_DSMEM);
    gemm_qkv_kernel<<<dim3(6, 64, 3), 256, GEMM_DSMEM>>>();

    cudaFuncSetAttribute(attn_kernel, cudaFuncAttributeMaxDynamicSharedMemorySize, ATTN_SMEM);
    attn_kernel<<<dim3(Nq / 128, Hq, Bq), 256, ATTN_SMEM>>>();

    cudaFuncSetAttribute(gemm_out_kernel, cudaFuncAttributeMaxDynamicSharedMemorySize, GEMM_DSMEM);
    gemm_out_kernel<<<dim3(6, 64), 256, GEMM_DSMEM>>>(bp, out);
}

// round 7
// speedup vs baseline: 2.4728x; 2.4728x over previous
#include <cuda_runtime.h>
#include <cuda_bf16.h>
#include <cstdint>

#define Bq 8
#define Nq 1024
#define Cq 768
#define Hq 12
#define HDq 64
#define Rq 16
#define ROWS (Bq*Nq)
#define SCALE 0.125f

typedef __nv_bfloat16 bf16;

// ---------------- mma.sync / ldmatrix / cp.async helpers ----------------
__device__ __forceinline__ uint32_t smem_u32(const void* p) {
    uint32_t a;
    asm("{ .reg .u64 t; cvta.to.shared.u64 t, %1; cvt.u32.u64 %0, t; }" : "=r"(a) : "l"(p));
    return a;
}
__device__ __forceinline__ void ldsm4(uint32_t& r0, uint32_t& r1, uint32_t& r2, uint32_t& r3,
                                      uint32_t addr) {
    asm volatile("ldmatrix.sync.aligned.m8n8.x4.shared.b16 {%0,%1,%2,%3}, [%4];"
                 : "=r"(r0), "=r"(r1), "=r"(r2), "=r"(r3) : "r"(addr));
}
__device__ __forceinline__ void ldsm4t(uint32_t& r0, uint32_t& r1, uint32_t& r2, uint32_t& r3,
                                       uint32_t addr) {
    asm volatile("ldmatrix.sync.aligned.m8n8.x4.trans.shared.b16 {%0,%1,%2,%3}, [%4];"
                 : "=r"(r0), "=r"(r1), "=r"(r2), "=r"(r3) : "r"(addr));
}
__device__ __forceinline__ void mma_bf16(float* c, uint32_t a0, uint32_t a1, uint32_t a2,
                                         uint32_t a3, uint32_t b0, uint32_t b1) {
    asm("mma.sync.aligned.m16n8k16.row.col.f32.bf16.bf16.f32 "
        "{%0,%1,%2,%3}, {%4,%5,%6,%7}, {%8,%9}, {%0,%1,%2,%3};"
        : "+f"(c[0]), "+f"(c[1]), "+f"(c[2]), "+f"(c[3])
        : "r"(a0), "r"(a1), "r"(a2), "r"(a3), "r"(b0), "r"(b1));
}
__device__ __forceinline__ void cp16(uint32_t dst, const void* src) {
    asm volatile("cp.async.cg.shared.global [%0], [%1], 16;" :: "r"(dst), "l"(src));
}
__device__ __forceinline__ void cp_commit() {
    asm volatile("cp.async.commit_group;" ::: "memory");
}
template <int N>
__device__ __forceinline__ void cp_wait() {
    asm volatile("cp.async.wait_group %0;" :: "n"(N) : "memory");
}

__device__ __forceinline__ void split_bf16(float v, bf16& h, bf16& l) {
    h = __float2bfloat16(v);
    l = __float2bfloat16(v - __bfloat162float(h));
}
__device__ __forceinline__ uint32_t pkbf(bf16 a, bf16 b) {
    __nv_bfloat162 t; t.x = a; t.y = b;
    return *(uint32_t*)&t;
}
__device__ __forceinline__ bf16 hi_bf(float v) { return __float2bfloat16(v); }

// ---------------- scratch ----------------
__device__ bf16 g_qh[Bq*Hq*Nq*HDq], g_ql[Bq*Hq*Nq*HDq];
__device__ bf16 g_kh[Bq*Hq*Nq*HDq], g_kl[Bq*Hq*Nq*HDq];
__device__ bf16 g_vh[Bq*Hq*Nq*HDq], g_vl[Bq*Hq*Nq*HDq];
__device__ bf16 g_Xh[ROWS*Cq], g_Xl[ROWS*Cq];
__device__ bf16 g_Wth[3][Cq*Cq], g_Wtl[3][Cq*Cq];     // (W + bw*la@lb)^T hi/lo
__device__ bf16 g_Wpth[Cq*Cq], g_Wptl[Cq*Cq];
__device__ bf16 g_atth[ROWS*Cq], g_attl[ROWS*Cq];

// ---------------- prep kernels ----------------
__global__ void convert_x_kernel(const float* __restrict__ X) {
    int i = blockIdx.x * blockDim.x + threadIdx.x;
    if (i < ROWS * Cq) {
        bf16 h, l; split_bf16(X[i], h, l);
        g_Xh[i] = h; g_Xl[i] = l;
    }
}

// W' = W + bw*(la@lb)  (sel<3), or plain Wp (sel=3); write transposed hi/lo
__global__ __launch_bounds__(256) void wprime_kernel(
        const float* __restrict__ Wq_, const float* __restrict__ Wk_,
        const float* __restrict__ Wv_, const float* __restrict__ Wp_,
        const float* __restrict__ laq, const float* __restrict__ lbq,
        const float* __restrict__ lak, const float* __restrict__ lbk,
        const float* __restrict__ lav, const float* __restrict__ lbv,
        const float* __restrict__ bw) {
    __shared__ float ws[32][33];
    __shared__ float las[32][16];
    __shared__ float lbs[16][33];
    int sel = blockIdx.z;
    const float* W  = (sel == 0) ? Wq_ : (sel == 1) ? Wk_ : (sel == 2) ? Wv_ : Wp_;
    const float* la = (sel == 0) ? laq : (sel == 1) ? lak : lav;
    const float* lb = (sel == 0) ? lbq : (sel == 1) ? lbk : lbv;
    bf16* dh = (sel < 3) ? g_Wth[sel] : g_Wpth;
    bf16* dl = (sel < 3) ? g_Wtl[sel] : g_Wptl;
    int tid = threadIdx.x, tx = tid & 31, ty = tid >> 5;
    int kb = blockIdx.y * 32, nb = blockIdx.x * 32;
    #pragma unroll
    for (int s = 0; s < 4; s++)
        ws[ty + 8 * s][tx] = W[(size_t)(kb + ty + 8 * s) * Cq + nb + tx];
    if (sel < 3) {
        for (int l = tid; l < 512; l += 256) {
            las[l >> 4][l & 15] = la[(size_t)(kb + (l >> 4)) * Rq + (l & 15)];
            lbs[l >> 5][l & 31] = lb[(size_t)(l >> 5) * Cq + nb + (l & 31)];
        }
        __syncthreads();
        float w = bw[sel];
        #pragma unroll
        for (int s = 0; s < 4; s++) {
            int i = ty + 8 * s;
            float acc = 0.f;
            #pragma unroll
            for (int r = 0; r < Rq; r++) acc = fmaf(las[i][r], lbs[r][tx], acc);
            ws[i][tx] = fmaf(w, acc, ws[i][tx]);
        }
    }
    __syncthreads();
    #pragma unroll
    for (int s = 0; s < 4; s++) {
        float v = ws[tx][ty + 8 * s];
        bf16 h, l; split_bf16(v, h, l);
        size_t idx = (size_t)(nb + ty + 8 * s) * Cq + kb + tx;
        dh[idx] = h; dl[idx] = l;
    }
}

// ---------------- pipelined bf16 GEMM core ----------------
#define PITCH 40
#define NSTAGE 4
#define TILE_B 10240
#define STAGE_B (4*TILE_B)
#define GEMM_DSMEM (NSTAGE*STAGE_B)

__device__ __forceinline__ void issue_chunk(uint32_t sbase, int stage,
                                            const bf16* ah, const bf16* al,
                                            const bf16* bh, const bf16* bl,
                                            int stride, int tid) {
    uint32_t st = sbase + stage * STAGE_B;
    const bf16* srcs[4] = {ah, al, bh, bl};
    #pragma unroll
    for (int t = 0; t < 4; t++) {
        #pragma unroll
        for (int i = 0; i < 2; i++) {
            int idx = tid + 256 * i;
            int row = idx >> 2, seg = idx & 3;
            cp16(st + t * TILE_B + (row * PITCH + seg * 8) * 2,
                 srcs[t] + (size_t)row * stride + seg * 8);
        }
    }
    cp_commit();
}

__device__ __forceinline__ void compute_chunk(uint32_t sbase, int stage,
                                              float C[2][8][4], int a_off, int b_off) {
    uint32_t st = sbase + stage * STAGE_B;
    uint32_t aH = st, aL = st + TILE_B, bH = st + 2 * TILE_B, bL = st + 3 * TILE_B;
    #pragma unroll
    for (int kt = 0; kt < 2; kt++) {
        int ko = kt * 16;
        uint32_t ah[2][4], al[2][4], bh[8][2], bl[8][2];
        #pragma unroll
        for (int mt = 0; mt < 2; mt++) {
            int off = (a_off + mt * 16 * PITCH + ko) * 2;
            ldsm4(ah[mt][0], ah[mt][1], ah[mt][2], ah[mt][3], aH + off);
            ldsm4(al[mt][0], al[mt][1], al[mt][2], al[mt][3], aL + off);
        }
        #pragma unroll
        for (int p = 0; p < 4; p++) {
            int off = (b_off + p * 16 * PITCH + ko) * 2;
            ldsm4(bh[2*p][0], bh[2*p][1], bh[2*p+1][0], bh[2*p+1][1], bH + off);
            ldsm4(bl[2*p][0], bl[2*p][1], bl[2*p+1][0], bl[2*p+1][1], bL + off);
        }
        #pragma unroll
        for (int mt = 0; mt < 2; mt++)
            #pragma unroll
            for (int nt = 0; nt < 8; nt++) {
                mma_bf16(C[mt][nt], ah[mt][0], ah[mt][1], ah[mt][2], ah[mt][3],
                         bh[nt][0], bh[nt][1]);
                mma_bf16(C[mt][nt], ah[mt][0], ah[mt][1], ah[mt][2], ah[mt][3],
                         bl[nt][0], bl[nt][1]);
                mma_bf16(C[mt][nt], al[mt][0], al[mt][1], al[mt][2], al[mt][3],
                         bh[nt][0], bh[nt][1]);
            }
    }
}

// ---------------- qkv GEMM (LoRA folded into W') -> bf16 hi/lo head-split ----------------
__global__ __launch_bounds__(256) void gemm_qkv_kernel() {
    extern __shared__ char dsm[];
    uint32_t sbase = smem_u32(dsm);
    int tid = threadIdx.x, lid = tid & 31, wid = tid >> 5;
    int wm = (wid & 3) * 32, wn = (wid >> 2) * 64;
    int type = blockIdx.z;
    int rowBase = blockIdx.y * 128, colBase = blockIdx.x * 128;

    const bf16* Xh = g_Xh + (size_t)rowBase * Cq;
    const bf16* Xl = g_Xl + (size_t)rowBase * Cq;
    const bf16* Wh = g_Wth[type] + (size_t)colBase * Cq;
    const bf16* Wl = g_Wtl[type] + (size_t)colBase * Cq;

    float C[2][8][4];
    #pragma unroll
    for (int i = 0; i < 2; i++)
        #pragma unroll
        for (int j = 0; j < 8; j++)
            #pragma unroll
            for (int k = 0; k < 4; k++) C[i][j][k] = 0.f;

    int a_off = (wm + (lid & 15)) * PITCH + ((lid >> 4) & 1) * 8;
    int b_off = (wn + ((lid >> 4) & 1) * 8 + (lid & 7)) * PITCH + ((lid >> 3) & 1) * 8;

    const int NCH = 24;
    #pragma unroll
    for (int s = 0; s < NSTAGE - 1; s++)
        issue_chunk(sbase, s, Xh + s * 32, Xl + s * 32, Wh + s * 32, Wl + s * 32, Cq, tid);
    for (int c = 0; c < NCH; c++) {
        cp_wait<NSTAGE - 2>();
        __syncthreads();
        int nc = c + NSTAGE - 1;
        if (nc < NCH)
            issue_chunk(sbase, nc & (NSTAGE - 1), Xh + nc * 32, Xl + nc * 32,
                        Wh + nc * 32, Wl + nc * 32, Cq, tid);
        else
            cp_commit();
        compute_chunk(sbase, c & (NSTAGE - 1), C, a_off, b_off);
    }

    bf16* outh = (type == 0) ? g_qh : (type == 1) ? g_kh : g_vh;
    bf16* outl = (type == 0) ? g_ql : (type == 1) ? g_kl : g_vl;
    float scl = (type == 0) ? SCALE : 1.f;
    #pragma unroll
    for (int mt = 0; mt < 2; mt++)
        #pragma unroll
        for (int nt = 0; nt < 8; nt++) {
            int col = colBase + wn + nt * 8 + (lid & 3) * 2;
            int h = col >> 6, hd = col & 63;
            #pragma unroll
            for (int half = 0; half < 2; half++) {
                int row = rowBase + wm + mt * 16 + (lid >> 2) + half * 8;
                int b_ = row >> 10, n = row & 1023;
                float v0 = C[mt][nt][half * 2] * scl, v1 = C[mt][nt][half * 2 + 1] * scl;
                bf16 h0, l0, h1, l1;
                split_bf16(v0, h0, l0); split_bf16(v1, h1, l1);
                size_t base = (((size_t)(b_ * Hq + h) * Nq) + n) * HDq + hd;
                *(uint32_t*)&outh[base] = pkbf(h0, h1);
                *(uint32_t*)&outl[base] = pkbf(l0, l1);
            }
        }
}

// ---------------- output projection GEMM + bias ----------------
__global__ __launch_bounds__(256) void gemm_out_kernel(const float* __restrict__ bias,
                                                       float* __restrict__ out) {
    extern __shared__ char dsm[];
    uint32_t sbase = smem_u32(dsm);
    int tid = threadIdx.x, lid = tid & 31, wid = tid >> 5;
    int wm = (wid & 3) * 32, wn = (wid >> 2) * 64;
    int rowBase = blockIdx.y * 128, colBase = blockIdx.x * 128;

    const bf16* Ah = g_atth + (size_t)rowBase * Cq;
    const bf16* Al = g_attl + (size_t)rowBase * Cq;
    const bf16* Wh = g_Wpth + (size_t)colBase * Cq;
    const bf16* Wl = g_Wptl + (size_t)colBase * Cq;

    float C[2][8][4];
    #pragma unroll
    for (int i = 0; i < 2; i++)
        #pragma unroll
        for (int j = 0; j < 8; j++)
            #pragma unroll
            for (int k = 0; k < 4; k++) C[i][j][k] = 0.f;

    int a_off = (wm + (lid & 15)) * PITCH + ((lid >> 4) & 1) * 8;
    int b_off = (wn + ((lid >> 4) & 1) * 8 + (lid & 7)) * PITCH + ((lid >> 3) & 1) * 8;

    const int NCH = 24;
    #pragma unroll
    for (int s = 0; s < NSTAGE - 1; s++)
        issue_chunk(sbase, s, Ah + s * 32, Al + s * 32, Wh + s * 32, Wl + s * 32, Cq, tid);
    for (int c = 0; c < NCH; c++) {
        cp_wait<NSTAGE - 2>();
        __syncthreads();
        int nc = c + NSTAGE - 1;
        if (nc < NCH)
            issue_chunk(sbase, nc & (NSTAGE - 1), Ah + nc * 32, Al + nc * 32,
                        Wh + nc * 32, Wl + nc * 32, Cq, tid);
        else
            cp_commit();
        compute_chunk(sbase, c & (NSTAGE - 1), C, a_off, b_off);
    }

    #pragma unroll
    for (int mt = 0; mt < 2; mt++)
        #pragma unroll
        for (int nt = 0; nt < 8; nt++) {
            int col = colBase + wn + nt * 8 + (lid & 3) * 2;
            float2 bv = *(const float2*)&bias[col];
            #pragma unroll
            for (int half = 0; half < 2; half++) {
                int row = rowBase + wm + mt * 16 + (lid >> 2) + half * 8;
                float2 v = make_float2(C[mt][nt][half * 2] + bv.x, C[mt][nt][half * 2 + 1] + bv.y);
                *(float2*)&out[(size_t)row * Cq + col] = v;
            }
        }
}

// ---------------- FA2-style mma attention: warp = 16 rows, full n=64, register softmax --------
#define KVP 72
#define QBYTES 18432                 // 128*72*2
#define KVTILE 9216                  // 64*72*2
#define KVBUF (4*KVTILE)             // Kh,Kl,Vh,Vl
#define AOFF_KV (2*QBYTES)
#define ATTN_SMEM (2*QBYTES + 2*KVBUF)   // 110592

__global__ __launch_bounds__(256) void attn_kernel() {
    extern __shared__ char smx[];
    uint32_t sb = smem_u32(smx);
    int tid = threadIdx.x, lid = tid & 31, wid = tid >> 5;
    int wm = wid * 16;
    int qt = blockIdx.x, head = blockIdx.y, b = blockIdx.z;
    size_t bh = (size_t)(b * Hq + head) * Nq * HDq;
    const bf16* Qhg = g_qh + bh + (size_t)qt * 128 * HDq;
    const bf16* Qlg = g_ql + bh + (size_t)qt * 128 * HDq;

    // prologue: Q (hi+lo) and KV tile 0, one group
    #pragma unroll
    for (int i = 0; i < 4; i++) {
        int idx = tid + 256 * i;
        int row = idx >> 3, seg = idx & 7;
        cp16(sb + (row * KVP + seg * 8) * 2, Qhg + row * HDq + seg * 8);
        cp16(sb + QBYTES + (row * KVP + seg * 8) * 2, Qlg + row * HDq + seg * 8);
    }
    {
        const bf16* srcs[4] = {g_kh + bh, g_kl + bh, g_vh + bh, g_vl + bh};
        #pragma unroll
        for (int t = 0; t < 4; t++)
            #pragma unroll
            for (int i = 0; i < 2; i++) {
                int idx = tid + 256 * i;
                int row = idx >> 3, seg = idx & 7;
                cp16(sb + AOFF_KV + t * KVTILE + (row * KVP + seg * 8) * 2,
                     srcs[t] + row * HDq + seg * 8);
            }
    }
    cp_commit();

    float mA = -1e30f, mB = -1e30f, lA = 0.f, lB = 0.f;
    float co[8][4];
    #pragma unroll
    for (int j = 0; j < 8; j++)
        #pragma unroll
        for (int k = 0; k < 4; k++) co[j][k] = 0.f;

    for (int it = 0; it < 16; it++) {
        if (it + 1 < 16) {
            uint32_t dst = sb + AOFF_KV + ((it + 1) & 1) * KVBUF;
            const bf16* srcs[4] = {g_kh + bh + (size_t)(it + 1) * 64 * HDq,
                                   g_kl + bh + (size_t)(it + 1) * 64 * HDq,
                                   g_vh + bh + (size_t)(it + 1) * 64 * HDq,
                                   g_vl + bh + (size_t)(it + 1) * 64 * HDq};
            #pragma unroll
            for (int t = 0; t < 4; t++)
                #pragma unroll
                for (int i = 0; i < 2; i++) {
                    int idx = tid + 256 * i;
                    int row = idx >> 3, seg = idx & 7;
                    cp16(dst + t * KVTILE + (row * KVP + seg * 8) * 2,
                         srcs[t] + row * HDq + seg * 8);
                }
        }
        cp_commit();
        cp_wait<1>();
        __syncthreads();

        uint32_t kv = sb + AOFF_KV + (it & 1) * KVBUF;
        uint32_t aKh = kv, aKl = kv + KVTILE, aVh = kv + 2 * KVTILE, aVl = kv + 3 * KVTILE;

        // ---- S = Q K^T : m16 x n64 per warp, 3-pass ----
        float cs[8][4];
        #pragma unroll
        for (int j = 0; j < 8; j++)
            #pragma unroll
            for (int k = 0; k < 4; k++) cs[j][k] = 0.f;

        #pragma unroll
        for (int ks = 0; ks < 4; ks++) {
            int ko = ks * 16;
            uint32_t qh[4], ql[4], kh[8][2], kl[8][2];
            int offq = ((wm + (lid & 15)) * KVP + ((lid >> 4) & 1) * 8 + ko) * 2;
            ldsm4(qh[0], qh[1], qh[2], qh[3], sb + offq);
            ldsm4(ql[0], ql[1], ql[2], ql[3], sb + QBYTES + offq);
            #pragma unroll
            for (int p = 0; p < 4; p++) {
                int offb = ((p * 16 + ((lid >> 4) & 1) * 8 + (lid & 7)) * KVP
                            + ((lid >> 3) & 1) * 8 + ko) * 2;
                ldsm4(kh[2*p][0], kh[2*p][1], kh[2*p+1][0], kh[2*p+1][1], aKh + offb);
                ldsm4(kl[2*p][0], kl[2*p][1], kl[2*p+1][0], kl[2*p+1][1], aKl + offb);
            }
            #pragma unroll
            for (int nt = 0; nt < 8; nt++) {
                mma_bf16(cs[nt], qh[0], qh[1], qh[2], qh[3], kh[nt][0], kh[nt][1]);
                mma_bf16(cs[nt], qh[0], qh[1], qh[2], qh[3], kl[nt][0], kl[nt][1]);
                mma_bf16(cs[nt], ql[0], ql[1], ql[2], ql[3], kh[nt][0], kh[nt][1]);
            }
        }

        // ---- register softmax (rows rA = wm+lid/4, rB = rA+8) ----
        float mxA = -1e30f, mxB = -1e30f;
        #pragma unroll
        for (int nt = 0; nt < 8; nt++) {
            mxA = fmaxf(mxA, fmaxf(cs[nt][0], cs[nt][1]));
            mxB = fmaxf(mxB, fmaxf(cs[nt][2], cs[nt][3]));
        }
        mxA = fmaxf(mxA, __shfl_xor_sync(0xffffffffu, mxA, 1));
        mxA = fmaxf(mxA, __shfl_xor_sync(0xffffffffu, mxA, 2));
        mxB = fmaxf(mxB, __shfl_xor_sync(0xffffffffu, mxB, 1));
        mxB = fmaxf(mxB, __shfl_xor_sync(0xffffffffu, mxB, 2));
        float mnA = fmaxf(mA, mxA), mnB = fmaxf(mB, mxB);
        float alA = __expf(mA - mnA), alB = __expf(mB - mnB);
        float psA = 0.f, psB = 0.f;
        #pragma unroll
        for (int nt = 0; nt < 8; nt++) {
            cs[nt][0] = __expf(cs[nt][0] - mnA);
            cs[nt][1] = __expf(cs[nt][1] - mnA);
            cs[nt][2] = __expf(cs[nt][2] - mnB);
            cs[nt][3] = __expf(cs[nt][3] - mnB);
            psA += cs[nt][0] + cs[nt][1];
            psB += cs[nt][2] + cs[nt][3];
        }
        psA += __shfl_xor_sync(0xffffffffu, psA, 1);
        psA += __shfl_xor_sync(0xffffffffu, psA, 2);
        psB += __shfl_xor_sync(0xffffffffu, psB, 1);
        psB += __shfl_xor_sync(0xffffffffu, psB, 2);
        lA = lA * alA + psA; mA = mnA;
        lB = lB * alB + psB; mB = mnB;

        // ---- repack P c-frags -> a-frags (hi/lo) in registers ----
        uint32_t pah[4][4], pal[4][4];
        #pragma unroll
        for (int ks = 0; ks < 4; ks++) {
            #pragma unroll
            for (int half = 0; half < 2; half++) {
                int nt = 2 * ks + half;
                bf16 h0, l0, h1, l1, h2, l2, h3, l3;
                split_bf16(cs[nt][0], h0, l0); split_bf16(cs[nt][1], h1, l1);
                split_bf16(cs[nt][2], h2, l2); split_bf16(cs[nt][3], h3, l3);
                pah[ks][2 * half]     = pkbf(h0, h1);
                pah[ks][2 * half + 1] = pkbf(h2, h3);
                pal[ks][2 * half]     = pkbf(l0, l1);
                pal[ks][2 * half + 1] = pkbf(l2, l3);
            }
        }

        // ---- rescale O, O += P V (3-pass, V via ldmatrix.trans) ----
        #pragma unroll
        for (int nt = 0; nt < 8; nt++) {
            co[nt][0] *= alA; co[nt][1] *= alA;
            co[nt][2] *= alB; co[nt][3] *= alB;
        }
        #pragma unroll
        for (int ks = 0; ks < 4; ks++) {
            int ko = ks * 16;
            uint32_t vh[8][2], vl[8][2];
            #pragma unroll
            for (int dt = 0; dt < 4; dt++) {
                int offv = ((ko + (lid & 15)) * KVP + dt * 16 + ((lid >> 4) & 1) * 8) * 2;
                ldsm4t(vh[2*dt][0], vh[2*dt][1], vh[2*dt+1][0], vh[2*dt+1][1], aVh + offv);
                ldsm4t(vl[2*dt][0], vl[2*dt][1], vl[2*dt+1][0], vl[2*dt+1][1], aVl + offv);
            }
            #pragma unroll
            for (int nt = 0; nt < 8; nt++) {
                mma_bf16(co[nt], pah[ks][0], pah[ks][1], pah[ks][2], pah[ks][3],
                         vh[nt][0], vh[nt][1]);
                mma_bf16(co[nt], pah[ks][0], pah[ks][1], pah[ks][2], pah[ks][3],
                         vl[nt][0], vl[nt][1]);
                mma_bf16(co[nt], pal[ks][0], pal[ks][1], pal[ks][2], pal[ks][3],
                         vh[nt][0], vh[nt][1]);
            }
        }
        __syncthreads();
    }

    // ---- epilogue: normalize, write bf16 hi/lo to g_att [B,N,C] ----
    float invA = 1.f / lA, invB = 1.f / lB;
    int rA = qt * 128 + wm + (lid >> 2);
    #pragma unroll
    for (int nt = 0; nt < 8; nt++) {
        int col = head * HDq + nt * 8 + (lid & 3) * 2;
        float v0 = co[nt][0] * invA, v1 = co[nt][1] * invA;
        float v2 = co[nt][2] * invB, v3 = co[nt][3] * invB;
        bf16 h0, l0, h1, l1;
        split_bf16(v0, h0, l0); split_bf16(v1, h1, l1);
        size_t base = (size_t)(b * Nq + rA) * Cq + col;
        *(uint32_t*)&g_atth[base] = pkbf(h0, h1);
        *(uint32_t*)&g_attl[base] = pkbf(l0, l1);
        split_bf16(v2, h0, l0); split_bf16(v3, h1, l1);
        size_t base2 = (size_t)(b * Nq + rA + 8) * Cq + col;
        *(uint32_t*)&g_atth[base2] = pkbf(h0, h1);
        *(uint32_t*)&g_attl[base2] = pkbf(l0, l1);
    }
}

extern "C" void kernel_launch(void* const* d_in, const int* in_sizes, int n_in,
                              void* d_out, int out_size) {
    const float* x    = (const float*)d_in[0];
    const float* Wq   = (const float*)d_in[1];
    const float* Wk   = (const float*)d_in[2];
    const float* Wv   = (const float*)d_in[3];
    const float* Wp   = (const float*)d_in[4];
    const float* bp   = (const float*)d_in[5];
    const float* la_q = (const float*)d_in[6];
    const float* lb_q = (const float*)d_in[7];
    const float* la_k = (const float*)d_in[8];
    const float* lb_k = (const float*)d_in[9];
    const float* la_v = (const float*)d_in[10];
    const float* lb_v = (const float*)d_in[11];
    const float* bw   = (const float*)d_in[12];
    float* out = (float*)d_out;

    convert_x_kernel<<<(ROWS * Cq + 255) / 256, 256>>>(x);
    wprime_kernel<<<dim3(24, 24, 4), 256>>>(Wq, Wk, Wv, Wp,
                                            la_q, lb_q, la_k, lb_k, la_v, lb_v, bw);

    cudaFuncSetAttribute(gemm_qkv_kernel, cudaFuncAttributeMaxDynamicSharedMemorySize, GEMM_DSMEM);
    gemm_qkv_kernel<<<dim3(6, 64, 3), 256, GEMM_DSMEM>>>();

    cudaFuncSetAttribute(attn_kernel, cudaFuncAttributeMaxDynamicSharedMemorySize, ATTN_SMEM);
    attn_kernel<<<dim3(Nq / 128, Hq, Bq), 256, ATTN_SMEM>>>();

    cudaFuncSetAttribute(gemm_out_kernel, cudaFuncAttributeMaxDynamicSharedMemorySize, GEMM_DSMEM);
    gemm_out_kernel<<<dim3(6, 64), 256, GEMM_DSMEM>>>(bp, out);
}

// round 8
// speedup vs baseline: 2.6724x; 1.0807x over previous
#include <cuda_runtime.h>
#include <cuda_bf16.h>
#include <cstdint>

#define Bq 8
#define Nq 1024
#define Cq 768
#define Hq 12
#define HDq 64
#define Rq 16
#define ROWS (Bq*Nq)
#define SCALE 0.125f

typedef __nv_bfloat16 bf16;

// ---------------- mma.sync / ldmatrix / cp.async helpers ----------------
__device__ __forceinline__ uint32_t smem_u32(const void* p) {
    uint32_t a;
    asm("{ .reg .u64 t; cvta.to.shared.u64 t, %1; cvt.u32.u64 %0, t; }" : "=r"(a) : "l"(p));
    return a;
}
__device__ __forceinline__ void ldsm4(uint32_t& r0, uint32_t& r1, uint32_t& r2, uint32_t& r3,
                                      uint32_t addr) {
    asm volatile("ldmatrix.sync.aligned.m8n8.x4.shared.b16 {%0,%1,%2,%3}, [%4];"
                 : "=r"(r0), "=r"(r1), "=r"(r2), "=r"(r3) : "r"(addr));
}
__device__ __forceinline__ void ldsm4t(uint32_t& r0, uint32_t& r1, uint32_t& r2, uint32_t& r3,
                                       uint32_t addr) {
    asm volatile("ldmatrix.sync.aligned.m8n8.x4.trans.shared.b16 {%0,%1,%2,%3}, [%4];"
                 : "=r"(r0), "=r"(r1), "=r"(r2), "=r"(r3) : "r"(addr));
}
__device__ __forceinline__ void mma_bf16(float* c, uint32_t a0, uint32_t a1, uint32_t a2,
                                         uint32_t a3, uint32_t b0, uint32_t b1) {
    asm("mma.sync.aligned.m16n8k16.row.col.f32.bf16.bf16.f32 "
        "{%0,%1,%2,%3}, {%4,%5,%6,%7}, {%8,%9}, {%0,%1,%2,%3};"
        : "+f"(c[0]), "+f"(c[1]), "+f"(c[2]), "+f"(c[3])
        : "r"(a0), "r"(a1), "r"(a2), "r"(a3), "r"(b0), "r"(b1));
}
__device__ __forceinline__ void cp16(uint32_t dst, const void* src) {
    asm volatile("cp.async.cg.shared.global [%0], [%1], 16;" :: "r"(dst), "l"(src));
}
__device__ __forceinline__ void cp_commit() {
    asm volatile("cp.async.commit_group;" ::: "memory");
}
template <int N>
__device__ __forceinline__ void cp_wait() {
    asm volatile("cp.async.wait_group %0;" :: "n"(N) : "memory");
}

__device__ __forceinline__ void split_bf16(float v, bf16& h, bf16& l) {
    h = __float2bfloat16(v);
    l = __float2bfloat16(v - __bfloat162float(h));
}
__device__ __forceinline__ uint32_t pkbf(bf16 a, bf16 b) {
    __nv_bfloat162 t; t.x = a; t.y = b;
    return *(uint32_t*)&t;
}

// ---------------- scratch ----------------
__device__ bf16 g_qh[Bq*Hq*Nq*HDq], g_ql[Bq*Hq*Nq*HDq];
__device__ bf16 g_kh[Bq*Hq*Nq*HDq], g_kl[Bq*Hq*Nq*HDq];
__device__ bf16 g_vh[Bq*Hq*Nq*HDq], g_vl[Bq*Hq*Nq*HDq];
__device__ bf16 g_Xh[ROWS*Cq], g_Xl[ROWS*Cq];
__device__ bf16 g_Wth[3][Cq*Cq], g_Wtl[3][Cq*Cq];     // (W + bw*la@lb)^T hi/lo
__device__ bf16 g_Wpth[Cq*Cq], g_Wptl[Cq*Cq];
__device__ bf16 g_atth[ROWS*Cq], g_attl[ROWS*Cq];

// ---------------- prep kernels ----------------
__global__ void convert_x_kernel(const float* __restrict__ X) {
    int i = blockIdx.x * blockDim.x + threadIdx.x;
    if (i < ROWS * Cq) {
        bf16 h, l; split_bf16(X[i], h, l);
        g_Xh[i] = h; g_Xl[i] = l;
    }
}

// W' = W + bw*(la@lb)  (sel<3), or plain Wp (sel=3); write transposed hi/lo
__global__ __launch_bounds__(256) void wprime_kernel(
        const float* __restrict__ Wq_, const float* __restrict__ Wk_,
        const float* __restrict__ Wv_, const float* __restrict__ Wp_,
        const float* __restrict__ laq, const float* __restrict__ lbq,
        const float* __restrict__ lak, const float* __restrict__ lbk,
        const float* __restrict__ lav, const float* __restrict__ lbv,
        const float* __restrict__ bw) {
    __shared__ float ws[32][33];
    __shared__ float las[32][16];
    __shared__ float lbs[16][33];
    int sel = blockIdx.z;
    const float* W  = (sel == 0) ? Wq_ : (sel == 1) ? Wk_ : (sel == 2) ? Wv_ : Wp_;
    const float* la = (sel == 0) ? laq : (sel == 1) ? lak : lav;
    const float* lb = (sel == 0) ? lbq : (sel == 1) ? lbk : lbv;
    bf16* dh = (sel < 3) ? g_Wth[sel] : g_Wpth;
    bf16* dl = (sel < 3) ? g_Wtl[sel] : g_Wptl;
    int tid = threadIdx.x, tx = tid & 31, ty = tid >> 5;
    int kb = blockIdx.y * 32, nb = blockIdx.x * 32;
    #pragma unroll
    for (int s = 0; s < 4; s++)
        ws[ty + 8 * s][tx] = W[(size_t)(kb + ty + 8 * s) * Cq + nb + tx];
    if (sel < 3) {
        for (int l = tid; l < 512; l += 256) {
            las[l >> 4][l & 15] = la[(size_t)(kb + (l >> 4)) * Rq + (l & 15)];
            lbs[l >> 5][l & 31] = lb[(size_t)(l >> 5) * Cq + nb + (l & 31)];
        }
        __syncthreads();
        float w = bw[sel];
        #pragma unroll
        for (int s = 0; s < 4; s++) {
            int i = ty + 8 * s;
            float acc = 0.f;
            #pragma unroll
            for (int r = 0; r < Rq; r++) acc = fmaf(las[i][r], lbs[r][tx], acc);
            ws[i][tx] = fmaf(w, acc, ws[i][tx]);
        }
    }
    __syncthreads();
    #pragma unroll
    for (int s = 0; s < 4; s++) {
        float v = ws[tx][ty + 8 * s];
        bf16 h, l; split_bf16(v, h, l);
        size_t idx = (size_t)(nb + ty + 8 * s) * Cq + kb + tx;
        dh[idx] = h; dl[idx] = l;
    }
}

// ---------------- pipelined bf16 GEMM core (double-buffer, 2 CTAs/SM) ----------------
#define PITCH 40
#define NSTAGE 2
#define TILE_B 10240
#define STAGE_B (4*TILE_B)
#define GEMM_DSMEM (NSTAGE*STAGE_B)        // 80KB -> 2 CTAs/SM

__device__ __forceinline__ void issue_chunk(uint32_t sbase, int stage,
                                            const bf16* ah, const bf16* al,
                                            const bf16* bh, const bf16* bl,
                                            int stride, int tid) {
    uint32_t st = sbase + stage * STAGE_B;
    const bf16* srcs[4] = {ah, al, bh, bl};
    #pragma unroll
    for (int t = 0; t < 4; t++) {
        #pragma unroll
        for (int i = 0; i < 2; i++) {
            int idx = tid + 256 * i;
            int row = idx >> 2, seg = idx & 3;
            cp16(st + t * TILE_B + (row * PITCH + seg * 8) * 2,
                 srcs[t] + (size_t)row * stride + seg * 8);
        }
    }
    cp_commit();
}

__device__ __forceinline__ void compute_chunk(uint32_t sbase, int stage,
                                              float C[2][8][4], int a_off, int b_off) {
    uint32_t st = sbase + stage * STAGE_B;
    uint32_t aH = st, aL = st + TILE_B, bH = st + 2 * TILE_B, bL = st + 3 * TILE_B;
    #pragma unroll
    for (int kt = 0; kt < 2; kt++) {
        int ko = kt * 16;
        uint32_t ah[2][4], al[2][4], bh[8][2], bl[8][2];
        #pragma unroll
        for (int mt = 0; mt < 2; mt++) {
            int off = (a_off + mt * 16 * PITCH + ko) * 2;
            ldsm4(ah[mt][0], ah[mt][1], ah[mt][2], ah[mt][3], aH + off);
            ldsm4(al[mt][0], al[mt][1], al[mt][2], al[mt][3], aL + off);
        }
        #pragma unroll
        for (int p = 0; p < 4; p++) {
            int off = (b_off + p * 16 * PITCH + ko) * 2;
            ldsm4(bh[2*p][0], bh[2*p][1], bh[2*p+1][0], bh[2*p+1][1], bH + off);
            ldsm4(bl[2*p][0], bl[2*p][1], bl[2*p+1][0], bl[2*p+1][1], bL + off);
        }
        #pragma unroll
        for (int mt = 0; mt < 2; mt++)
            #pragma unroll
            for (int nt = 0; nt < 8; nt++) {
                mma_bf16(C[mt][nt], ah[mt][0], ah[mt][1], ah[mt][2], ah[mt][3],
                         bh[nt][0], bh[nt][1]);
                mma_bf16(C[mt][nt], ah[mt][0], ah[mt][1], ah[mt][2], ah[mt][3],
                         bl[nt][0], bl[nt][1]);
                mma_bf16(C[mt][nt], al[mt][0], al[mt][1], al[mt][2], al[mt][3],
                         bh[nt][0], bh[nt][1]);
            }
    }
}

// ---------------- qkv GEMM (LoRA folded into W') -> bf16 hi/lo head-split ----------------
__global__ __launch_bounds__(256, 2) void gemm_qkv_kernel() {
    extern __shared__ char dsm[];
    uint32_t sbase = smem_u32(dsm);
    int tid = threadIdx.x, lid = tid & 31, wid = tid >> 5;
    int wm = (wid & 3) * 32, wn = (wid >> 2) * 64;
    int type = blockIdx.z;
    int rowBase = blockIdx.y * 128, colBase = blockIdx.x * 128;

    const bf16* Xh = g_Xh + (size_t)rowBase * Cq;
    const bf16* Xl = g_Xl + (size_t)rowBase * Cq;
    const bf16* Wh = g_Wth[type] + (size_t)colBase * Cq;
    const bf16* Wl = g_Wtl[type] + (size_t)colBase * Cq;

    float C[2][8][4];
    #pragma unroll
    for (int i = 0; i < 2; i++)
        #pragma unroll
        for (int j = 0; j < 8; j++)
            #pragma unroll
            for (int k = 0; k < 4; k++) C[i][j][k] = 0.f;

    int a_off = (wm + (lid & 15)) * PITCH + ((lid >> 4) & 1) * 8;
    int b_off = (wn + ((lid >> 4) & 1) * 8 + (lid & 7)) * PITCH + ((lid >> 3) & 1) * 8;

    const int NCH = 24;
    issue_chunk(sbase, 0, Xh, Xl, Wh, Wl, Cq, tid);
    for (int c = 0; c < NCH; c++) {
        cp_wait<0>();
        __syncthreads();
        int nc = c + 1;
        if (nc < NCH)
            issue_chunk(sbase, nc & 1, Xh + nc * 32, Xl + nc * 32,
                        Wh + nc * 32, Wl + nc * 32, Cq, tid);
        compute_chunk(sbase, c & 1, C, a_off, b_off);
    }

    bf16* outh = (type == 0) ? g_qh : (type == 1) ? g_kh : g_vh;
    bf16* outl = (type == 0) ? g_ql : (type == 1) ? g_kl : g_vl;
    float scl = (type == 0) ? SCALE : 1.f;
    #pragma unroll
    for (int mt = 0; mt < 2; mt++)
        #pragma unroll
        for (int nt = 0; nt < 8; nt++) {
            int col = colBase + wn + nt * 8 + (lid & 3) * 2;
            int h = col >> 6, hd = col & 63;
            #pragma unroll
            for (int half = 0; half < 2; half++) {
                int row = rowBase + wm + mt * 16 + (lid >> 2) + half * 8;
                int b_ = row >> 10, n = row & 1023;
                float v0 = C[mt][nt][half * 2] * scl, v1 = C[mt][nt][half * 2 + 1] * scl;
                bf16 h0, l0, h1, l1;
                split_bf16(v0, h0, l0); split_bf16(v1, h1, l1);
                size_t base = (((size_t)(b_ * Hq + h) * Nq) + n) * HDq + hd;
                *(uint32_t*)&outh[base] = pkbf(h0, h1);
                *(uint32_t*)&outl[base] = pkbf(l0, l1);
            }
        }
}

// ---------------- output projection GEMM + bias ----------------
__global__ __launch_bounds__(256, 2) void gemm_out_kernel(const float* __restrict__ bias,
                                                          float* __restrict__ out) {
    extern __shared__ char dsm[];
    uint32_t sbase = smem_u32(dsm);
    int tid = threadIdx.x, lid = tid & 31, wid = tid >> 5;
    int wm = (wid & 3) * 32, wn = (wid >> 2) * 64;
    int rowBase = blockIdx.y * 128, colBase = blockIdx.x * 128;

    const bf16* Ah = g_atth + (size_t)rowBase * Cq;
    const bf16* Al = g_attl + (size_t)rowBase * Cq;
    const bf16* Wh = g_Wpth + (size_t)colBase * Cq;
    const bf16* Wl = g_Wptl + (size_t)colBase * Cq;

    float C[2][8][4];
    #pragma unroll
    for (int i = 0; i < 2; i++)
        #pragma unroll
        for (int j = 0; j < 8; j++)
            #pragma unroll
            for (int k = 0; k < 4; k++) C[i][j][k] = 0.f;

    int a_off = (wm + (lid & 15)) * PITCH + ((lid >> 4) & 1) * 8;
    int b_off = (wn + ((lid >> 4) & 1) * 8 + (lid & 7)) * PITCH + ((lid >> 3) & 1) * 8;

    const int NCH = 24;
    issue_chunk(sbase, 0, Ah, Al, Wh, Wl, Cq, tid);
    for (int c = 0; c < NCH; c++) {
        cp_wait<0>();
        __syncthreads();
        int nc = c + 1;
        if (nc < NCH)
            issue_chunk(sbase, nc & 1, Ah + nc * 32, Al + nc * 32,
                        Wh + nc * 32, Wl + nc * 32, Cq, tid);
        compute_chunk(sbase, c & 1, C, a_off, b_off);
    }

    #pragma unroll
    for (int mt = 0; mt < 2; mt++)
        #pragma unroll
        for (int nt = 0; nt < 8; nt++) {
            int col = colBase + wn + nt * 8 + (lid & 3) * 2;
            float2 bv = *(const float2*)&bias[col];
            #pragma unroll
            for (int half = 0; half < 2; half++) {
                int row = rowBase + wm + mt * 16 + (lid >> 2) + half * 8;
                float2 v = make_float2(C[mt][nt][half * 2] + bv.x, C[mt][nt][half * 2 + 1] + bv.y);
                *(float2*)&out[(size_t)row * Cq + col] = v;
            }
        }
}

// ---------------- FA2-style mma attention: warp = 16 rows, register softmax ----------------
#define KVP 72
#define QBYTES 18432                 // 128*72*2
#define KVTILE 9216                  // 64*72*2
#define KVBUF (4*KVTILE)             // Kh,Kl,Vh,Vl
#define AOFF_KV (2*QBYTES)
#define ATTN_SMEM (2*QBYTES + 2*KVBUF)   // 110592

__global__ __launch_bounds__(256, 2) void attn_kernel() {
    extern __shared__ char smx[];
    uint32_t sb = smem_u32(smx);
    int tid = threadIdx.x, lid = tid & 31, wid = tid >> 5;
    int wm = wid * 16;
    int qt = blockIdx.x, head = blockIdx.y, b = blockIdx.z;
    size_t bh = (size_t)(b * Hq + head) * Nq * HDq;
    const bf16* Qhg = g_qh + bh + (size_t)qt * 128 * HDq;
    const bf16* Qlg = g_ql + bh + (size_t)qt * 128 * HDq;

    // prologue: Q (hi+lo) and KV tile 0
    #pragma unroll
    for (int i = 0; i < 4; i++) {
        int idx = tid + 256 * i;
        int row = idx >> 3, seg = idx & 7;
        cp16(sb + (row * KVP + seg * 8) * 2, Qhg + row * HDq + seg * 8);
        cp16(sb + QBYTES + (row * KVP + seg * 8) * 2, Qlg + row * HDq + seg * 8);
    }
    {
        const bf16* srcs[4] = {g_kh + bh, g_kl + bh, g_vh + bh, g_vl + bh};
        #pragma unroll
        for (int t = 0; t < 4; t++)
            #pragma unroll
            for (int i = 0; i < 2; i++) {
                int idx = tid + 256 * i;
                int row = idx >> 3, seg = idx & 7;
                cp16(sb + AOFF_KV + t * KVTILE + (row * KVP + seg * 8) * 2,
                     srcs[t] + row * HDq + seg * 8);
            }
    }
    cp_commit();

    float mA = -1e30f, mB = -1e30f, lA = 0.f, lB = 0.f;
    float co[8][4];
    #pragma unroll
    for (int j = 0; j < 8; j++)
        #pragma unroll
        for (int k = 0; k < 4; k++) co[j][k] = 0.f;

    for (int it = 0; it < 16; it++) {
        cp_wait<0>();
        __syncthreads();
        // issue next KV into other buffer (safe: all warps past barrier are done with it)
        if (it + 1 < 16) {
            uint32_t dst = sb + AOFF_KV + ((it + 1) & 1) * KVBUF;
            const bf16* srcs[4] = {g_kh + bh + (size_t)(it + 1) * 64 * HDq,
                                   g_kl + bh + (size_t)(it + 1) * 64 * HDq,
                                   g_vh + bh + (size_t)(it + 1) * 64 * HDq,
                                   g_vl + bh + (size_t)(it + 1) * 64 * HDq};
            #pragma unroll
            for (int t = 0; t < 4; t++)
                #pragma unroll
                for (int i = 0; i < 2; i++) {
                    int idx = tid + 256 * i;
                    int row = idx >> 3, seg = idx & 7;
                    cp16(dst + t * KVTILE + (row * KVP + seg * 8) * 2,
                         srcs[t] + row * HDq + seg * 8);
                }
            cp_commit();
        }

        uint32_t kv = sb + AOFF_KV + (it & 1) * KVBUF;
        uint32_t aKh = kv, aKl = kv + KVTILE, aVh = kv + 2 * KVTILE, aVl = kv + 3 * KVTILE;

        // ---- S = Q K^T : m16 x n64 per warp, 3-pass ----
        float cs[8][4];
        #pragma unroll
        for (int j = 0; j < 8; j++)
            #pragma unroll
            for (int k = 0; k < 4; k++) cs[j][k] = 0.f;

        #pragma unroll
        for (int ks = 0; ks < 4; ks++) {
            int ko = ks * 16;
            uint32_t qh[4], ql[4], kh[8][2], kl[8][2];
            int offq = ((wm + (lid & 15)) * KVP + ((lid >> 4) & 1) * 8 + ko) * 2;
            ldsm4(qh[0], qh[1], qh[2], qh[3], sb + offq);
            ldsm4(ql[0], ql[1], ql[2], ql[3], sb + QBYTES + offq);
            #pragma unroll
            for (int p = 0; p < 4; p++) {
                int offb = ((p * 16 + ((lid >> 4) & 1) * 8 + (lid & 7)) * KVP
                            + ((lid >> 3) & 1) * 8 + ko) * 2;
                ldsm4(kh[2*p][0], kh[2*p][1], kh[2*p+1][0], kh[2*p+1][1], aKh + offb);
                ldsm4(kl[2*p][0], kl[2*p][1], kl[2*p+1][0], kl[2*p+1][1], aKl + offb);
            }
            #pragma unroll
            for (int nt = 0; nt < 8; nt++) {
                mma_bf16(cs[nt], qh[0], qh[1], qh[2], qh[3], kh[nt][0], kh[nt][1]);
                mma_bf16(cs[nt], qh[0], qh[1], qh[2], qh[3], kl[nt][0], kl[nt][1]);
                mma_bf16(cs[nt], ql[0], ql[1], ql[2], ql[3], kh[nt][0], kh[nt][1]);
            }
        }

        // ---- register softmax ----
        float mxA = -1e30f, mxB = -1e30f;
        #pragma unroll
        for (int nt = 0; nt < 8; nt++) {
            mxA = fmaxf(mxA, fmaxf(cs[nt][0], cs[nt][1]));
            mxB = fmaxf(mxB, fmaxf(cs[nt][2], cs[nt][3]));
        }
        mxA = fmaxf(mxA, __shfl_xor_sync(0xffffffffu, mxA, 1));
        mxA = fmaxf(mxA, __shfl_xor_sync(0xffffffffu, mxA, 2));
        mxB = fmaxf(mxB, __shfl_xor_sync(0xffffffffu, mxB, 1));
        mxB = fmaxf(mxB, __shfl_xor_sync(0xffffffffu, mxB, 2));
        float mnA = fmaxf(mA, mxA), mnB = fmaxf(mB, mxB);
        float alA = __expf(mA - mnA), alB = __expf(mB - mnB);
        float psA = 0.f, psB = 0.f;
        #pragma unroll
        for (int nt = 0; nt < 8; nt++) {
            cs[nt][0] = __expf(cs[nt][0] - mnA);
            cs[nt][1] = __expf(cs[nt][1] - mnA);
            cs[nt][2] = __expf(cs[nt][2] - mnB);
            cs[nt][3] = __expf(cs[nt][3] - mnB);
            psA += cs[nt][0] + cs[nt][1];
            psB += cs[nt][2] + cs[nt][3];
        }
        psA += __shfl_xor_sync(0xffffffffu, psA, 1);
        psA += __shfl_xor_sync(0xffffffffu, psA, 2);
        psB += __shfl_xor_sync(0xffffffffu, psB, 1);
        psB += __shfl_xor_sync(0xffffffffu, psB, 2);
        lA = lA * alA + psA; mA = mnA;
        lB = lB * alB + psB; mB = mnB;

        // ---- repack P c-frags -> a-frags (hi/lo) in registers ----
        uint32_t pah[4][4], pal[4][4];
        #pragma unroll
        for (int ks = 0; ks < 4; ks++) {
            #pragma unroll
            for (int half = 0; half < 2; half++) {
                int nt = 2 * ks + half;
                bf16 h0, l0, h1, l1, h2, l2, h3, l3;
                split_bf16(cs[nt][0], h0, l0); split_bf16(cs[nt][1], h1, l1);
                split_bf16(cs[nt][2], h2, l2); split_bf16(cs[nt][3], h3, l3);
                pah[ks][2 * half]     = pkbf(h0, h1);
                pah[ks][2 * half + 1] = pkbf(h2, h3);
                pal[ks][2 * half]     = pkbf(l0, l1);
                pal[ks][2 * half + 1] = pkbf(l2, l3);
            }
        }

        // ---- rescale O, O += P V (3-pass, V via ldmatrix.trans) ----
        #pragma unroll
        for (int nt = 0; nt < 8; nt++) {
            co[nt][0] *= alA; co[nt][1] *= alA;
            co[nt][2] *= alB; co[nt][3] *= alB;
        }
        #pragma unroll
        for (int ks = 0; ks < 4; ks++) {
            int ko = ks * 16;
            uint32_t vh[8][2], vl[8][2];
            #pragma unroll
            for (int dt = 0; dt < 4; dt++) {
                int offv = ((ko + (lid & 15)) * KVP + dt * 16 + ((lid >> 4) & 1) * 8) * 2;
                ldsm4t(vh[2*dt][0], vh[2*dt][1], vh[2*dt+1][0], vh[2*dt+1][1], aVh + offv);
                ldsm4t(vl[2*dt][0], vl[2*dt][1], vl[2*dt+1][0], vl[2*dt+1][1], aVl + offv);
            }
            #pragma unroll
            for (int nt = 0; nt < 8; nt++) {
                mma_bf16(co[nt], pah[ks][0], pah[ks][1], pah[ks][2], pah[ks][3],
                         vh[nt][0], vh[nt][1]);
                mma_bf16(co[nt], pah[ks][0], pah[ks][1], pah[ks][2], pah[ks][3],
                         vl[nt][0], vl[nt][1]);
                mma_bf16(co[nt], pal[ks][0], pal[ks][1], pal[ks][2], pal[ks][3],
                         vh[nt][0], vh[nt][1]);
            }
        }
    }

    // ---- epilogue: normalize, write bf16 hi/lo to g_att [B,N,C] ----
    float invA = 1.f / lA, invB = 1.f / lB;
    int rA = qt * 128 + wm + (lid >> 2);
    #pragma unroll
    for (int nt = 0; nt < 8; nt++) {
        int col = head * HDq + nt * 8 + (lid & 3) * 2;
        float v0 = co[nt][0] * invA, v1 = co[nt][1] * invA;
        float v2 = co[nt][2] * invB, v3 = co[nt][3] * invB;
        bf16 h0, l0, h1, l1;
        split_bf16(v0, h0, l0); split_bf16(v1, h1, l1);
        size_t base = (size_t)(b * Nq + rA) * Cq + col;
        *(uint32_t*)&g_atth[base] = pkbf(h0, h1);
        *(uint32_t*)&g_attl[base] = pkbf(l0, l1);
        split_bf16(v2, h0, l0); split_bf16(v3, h1, l1);
        size_t base2 = (size_t)(b * Nq + rA + 8) * Cq + col;
        *(uint32_t*)&g_atth[base2] = pkbf(h0, h1);
        *(uint32_t*)&g_attl[base2] = pkbf(l0, l1);
    }
}

extern "C" void kernel_launch(void* const* d_in, const int* in_sizes, int n_in,
                              void* d_out, int out_size) {
    const float* x    = (const float*)d_in[0];
    const float* Wq   = (const float*)d_in[1];
    const float* Wk   = (const float*)d_in[2];
    const float* Wv   = (const float*)d_in[3];
    const float* Wp   = (const float*)d_in[4];
    const float* bp   = (const float*)d_in[5];
    const float* la_q = (const float*)d_in[6];
    const float* lb_q = (const float*)d_in[7];
    const float* la_k = (const float*)d_in[8];
    const float* lb_k = (const float*)d_in[9];
    const float* la_v = (const float*)d_in[10];
    const float* lb_v = (const float*)d_in[11];
    const float* bw   = (const float*)d_in[12];
    float* out = (float*)d_out;

    convert_x_kernel<<<(ROWS * Cq + 255) / 256, 256>>>(x);
    wprime_kernel<<<dim3(24, 24, 4), 256>>>(Wq, Wk, Wv, Wp,
                                            la_q, lb_q, la_k, lb_k, la_v, lb_v, bw);

    cudaFuncSetAttribute(gemm_qkv_kernel, cudaFuncAttributeMaxDynamicSharedMemorySize, GEMM_DSMEM);
    gemm_qkv_kernel<<<dim3(6, 64, 3), 256, GEMM_DSMEM>>>();

    cudaFuncSetAttribute(attn_kernel, cudaFuncAttributeMaxDynamicSharedMemorySize, ATTN_SMEM);
    attn_kernel<<<dim3(Nq / 128, Hq, Bq), 256, ATTN_SMEM>>>();

    cudaFuncSetAttribute(gemm_out_kernel, cudaFuncAttributeMaxDynamicSharedMemorySize, GEMM_DSMEM);
    gemm_out_kernel<<<dim3(6, 64), 256, GEMM_DSMEM>>>(bp, out);
}